// round 8
// baseline (speedup 1.0000x reference)
#include <cuda_runtime.h>
#include <cstdint>
#include <math.h>

#define BATCH 2
#define SEQ   2048
#define DMODEL 2048
#define NH    16
#define HD    128
#define CACHEDLEN 2048
#define TTOT  (CACHEDLEN + SEQ)      // 4096

// ---------------- scratch (static device globals) ----------------
__device__ float g_Q [(size_t)BATCH*NH*SEQ*HD];   // [B,H,S,HD] pre-scaled+rounded
__device__ float g_Kn[(size_t)BATCH*NH*SEQ*HD];   // [B,H,S,HD] rounded
__device__ float g_Vt[(size_t)BATCH*NH*HD*TTOT];  // [B,H,HD,T] rounded, transposed V (cache+new)
__device__ float g_At[(size_t)BATCH*SEQ*DMODEL];  // [B,S,D]    rounded
__device__ float g_X [(size_t)BATCH*SEQ*DMODEL];  // rounded hidden states
__device__ float g_Wr[(size_t)4*DMODEL*DMODEL];   // rounded Wq,Wk,Wv,Wo
__device__ float g_Kc[(size_t)BATCH*NH*CACHEDLEN*HD];  // rounded k_cache

// ================= helpers =================
__device__ __forceinline__ uint32_t smem_u32(const void* p) {
    uint32_t a;
    asm("{ .reg .u64 t; cvta.to.shared.u64 t, %1; cvt.u32.u64 %0, t; }" : "=r"(a) : "l"(p));
    return a;
}
__device__ __forceinline__ void cp_async16(uint32_t saddr, const void* gptr) {
    asm volatile("cp.async.cg.shared.global [%0], [%1], 16;\n" :: "r"(saddr), "l"(gptr));
}
#define CP_COMMIT() asm volatile("cp.async.commit_group;\n" ::: "memory")
#define CP_WAIT1()  asm volatile("cp.async.wait_group 1;\n" ::: "memory")

__device__ __forceinline__ uint32_t f2tf32(float f) {
    uint32_t r;
    asm("cvt.rna.tf32.f32 %0, %1;" : "=r"(r) : "f"(f));
    return r;
}
__device__ __forceinline__ float roundtf(float f) { return __uint_as_float(f2tf32(f)); }

__device__ __forceinline__ void mma_tf32(float c[4], const uint32_t a[4], const uint32_t b[2]) {
    asm volatile(
        "mma.sync.aligned.m16n8k8.row.col.f32.tf32.tf32.f32 "
        "{%0,%1,%2,%3}, {%4,%5,%6,%7}, {%8,%9}, {%0,%1,%2,%3};"
        : "+f"(c[0]), "+f"(c[1]), "+f"(c[2]), "+f"(c[3])
        : "r"(a[0]), "r"(a[1]), "r"(a[2]), "r"(a[3]), "r"(b[0]), "r"(b[1]));
}
__device__ __forceinline__ void ldsm_x4(uint32_t r[4], uint32_t saddr) {
    asm volatile("ldmatrix.sync.aligned.m8n8.x4.shared.b16 {%0,%1,%2,%3}, [%4];"
                 : "=r"(r[0]), "=r"(r[1]), "=r"(r[2]), "=r"(r[3]) : "r"(saddr));
}

// ================= tf32 pre-rounding kernel (4-wide) =================
__global__ __launch_bounds__(256) void round_tf32_k(const float4* __restrict__ in,
                                                    float4* __restrict__ out, int n4)
{
    int i = (blockIdx.x * blockDim.x + threadIdx.x) * 4;
    if (i + 3 < n4) {
        float4 a = in[i], b = in[i+1], c = in[i+2], d = in[i+3];
        a.x=roundtf(a.x); a.y=roundtf(a.y); a.z=roundtf(a.z); a.w=roundtf(a.w);
        b.x=roundtf(b.x); b.y=roundtf(b.y); b.z=roundtf(b.z); b.w=roundtf(b.w);
        c.x=roundtf(c.x); c.y=roundtf(c.y); c.z=roundtf(c.z); c.w=roundtf(c.w);
        d.x=roundtf(d.x); d.y=roundtf(d.y); d.z=roundtf(d.z); d.w=roundtf(d.w);
        out[i] = a; out[i+1] = b; out[i+2] = c; out[i+3] = d;
    }
}

// ============ v_cache: round + transpose [B,H,T,HD] -> [B,H,HD,T] ============
__global__ __launch_bounds__(256) void vtrans_round_k(const float* __restrict__ vc,
                                                      float* __restrict__ vt)
{
    __shared__ float tile[32][33];
    int bh = blockIdx.z;
    int t0 = blockIdx.x * 32, d0 = blockIdx.y * 32;
    int tx = threadIdx.x & 31, ty = threadIdx.x >> 5;   // ty 0..7
    const float* src = vc + ((size_t)bh * CACHEDLEN + t0) * HD + d0;
#pragma unroll
    for (int r = 0; r < 4; ++r) {
        int row = ty + r * 8;
        tile[row][tx] = roundtf(src[(size_t)row * HD + tx]);
    }
    __syncthreads();
    float* dst = vt + ((size_t)bh * HD + d0) * TTOT + t0;
#pragma unroll
    for (int r = 0; r < 4; ++r) {
        int row = ty + r * 8;
        dst[(size_t)row * TTOT + tx] = tile[tx][row];
    }
}

// ================= tf32 mma.sync GEMM =================
#define BK       32
#define NCHUNK   (DMODEL / BK)
#define ROWPAD   36
#define TILE_FLOATS (128 * ROWPAD)
#define STAGE_FLOATS (2 * TILE_FLOATS)
#define NSTAGES  3
#define GEMM_SMEM (NSTAGES * STAGE_FLOATS * 4)

__device__ __forceinline__ void load_stage(const float* __restrict__ A,
                                           const float* __restrict__ W,
                                           int m0, int n0, int k0,
                                           uint32_t sa, int tid)
{
#pragma unroll
    for (int i = 0; i < 4; ++i) {
        int c = tid + 256 * i;
        int row = c >> 3;
        int j = c & 7;
        cp_async16(sa + (uint32_t)(row * (ROWPAD * 4) + j * 16),
                   A + (size_t)(m0 + row) * DMODEL + k0 + j * 4);
    }
    uint32_t sb = sa + TILE_FLOATS * 4;
#pragma unroll
    for (int i = 0; i < 4; ++i) {
        int c = tid + 256 * i;
        int row = c >> 3;
        int j = c & 7;
        cp_async16(sb + (uint32_t)(row * (ROWPAD * 4) + j * 16),
                   W + (size_t)(n0 + row) * DMODEL + k0 + j * 4);
    }
}

__device__ __forceinline__ void gemm_body(const float* __restrict__ A,
                                          const float* __restrict__ W,
                                          uint32_t smb, int tid, int m0, int n0,
                                          float acc[4][4][4])
{
    int lane = tid & 31;
    int w = tid >> 5;
    int wm = w >> 2;
    int wn = w & 3;
    int lr16 = lane & 15;
    int lc4  = ((lane >> 4) & 1) * 4;
    int br   = (lane & 7) + ((lane >> 4) & 1) * 8;
    int bc4  = ((lane >> 3) & 1) * 4;
    uint32_t a_off[4], b_off[2];
#pragma unroll
    for (int mi = 0; mi < 4; ++mi)
        a_off[mi] = (uint32_t)(((wm * 64 + mi * 16 + lr16) * ROWPAD + lc4) * 4);
#pragma unroll
    for (int njp = 0; njp < 2; ++njp)
        b_off[njp] = (uint32_t)(((wn * 32 + njp * 16 + br) * ROWPAD + bc4) * 4);

    load_stage(A, W, m0, n0, 0, smb, tid);
    CP_COMMIT();
    load_stage(A, W, m0, n0, BK, smb + STAGE_FLOATS * 4, tid);
    CP_COMMIT();

    for (int it = 0; it < NCHUNK; ++it) {
        uint32_t sA = smb + (uint32_t)((it % NSTAGES) * STAGE_FLOATS * 4);
        uint32_t sB = sA + TILE_FLOATS * 4;
        CP_WAIT1();
        __syncthreads();

#pragma unroll
        for (int s = 0; s < 4; ++s) {
            uint32_t koff = (uint32_t)(s * 32);
            uint32_t af[4][4], bq[2][4];
#pragma unroll
            for (int mi = 0; mi < 4; ++mi) ldsm_x4(af[mi], sA + a_off[mi] + koff);
#pragma unroll
            for (int njp = 0; njp < 2; ++njp) ldsm_x4(bq[njp], sB + b_off[njp] + koff);
#pragma unroll
            for (int mi = 0; mi < 4; ++mi)
#pragma unroll
                for (int nj = 0; nj < 4; ++nj)
                    mma_tf32(acc[mi][nj], af[mi], &bq[nj >> 1][(nj & 1) * 2]);
        }

        if (it + 2 < NCHUNK)
            load_stage(A, W, m0, n0, (it + 2) * BK,
                       smb + (uint32_t)(((it + 2) % NSTAGES) * STAGE_FLOATS * 4), tid);
        CP_COMMIT();
    }
}

// Fused QKV projection: blockIdx.z selects proj (0=Q scaled, 1=K, 2=V transposed).
__global__ __launch_bounds__(256) void gemm_qkv(const float* __restrict__ A,
                                                const float* __restrict__ W0,
                                                float* __restrict__ Qo,
                                                float* __restrict__ Ko,
                                                float* __restrict__ Vt)
{
    extern __shared__ float sm[];
    uint32_t smb = smem_u32(sm);
    int tid = threadIdx.x;
    int pz = blockIdx.z;
    const float* W = W0 + (size_t)pz * DMODEL * DMODEL;
    float sc = (pz == 0) ? 0.088388347648318447f : 1.0f;
    int m0 = blockIdx.y * 128, n0 = blockIdx.x * 128;

    float acc[4][4][4];
#pragma unroll
    for (int i = 0; i < 4; ++i)
#pragma unroll
        for (int j = 0; j < 4; ++j)
#pragma unroll
            for (int r = 0; r < 4; ++r) acc[i][j][r] = 0.f;

    gemm_body(A, W, smb, tid, m0, n0, acc);

    int lane = tid & 31;
    int w = tid >> 5, wm = w >> 2, wn = w & 3;
    int g = lane >> 2, tg = lane & 3;
#pragma unroll
    for (int mi = 0; mi < 4; ++mi) {
#pragma unroll
        for (int nj = 0; nj < 4; ++nj) {
            int m = m0 + wm * 64 + mi * 16 + g;
            int n = n0 + wn * 32 + nj * 8 + 2 * tg;
            float v0 = roundtf(acc[mi][nj][0] * sc);
            float v1 = roundtf(acc[mi][nj][1] * sc);
            float v2 = roundtf(acc[mi][nj][2] * sc);
            float v3 = roundtf(acc[mi][nj][3] * sc);
            int h_  = n >> 7;
            int hd_ = n & 127;
            int b0 = m >> 11, s0 = m & 2047;
            int m2 = m + 8;
            int b1 = m2 >> 11, s1 = m2 & 2047;
            if (pz == 2) {
                // V transposed: [B,H,HD,TTOT], t = CACHEDLEN + s
                size_t base0 = (((size_t)b0 * NH + h_) * HD + hd_) * TTOT + CACHEDLEN;
                size_t base1 = (((size_t)b1 * NH + h_) * HD + hd_) * TTOT + CACHEDLEN;
                Vt[base0 + s0] = v0;
                Vt[base0 + TTOT + s0] = v1;
                Vt[base1 + s1] = v2;
                Vt[base1 + TTOT + s1] = v3;
            } else {
                float* C = (pz == 0) ? Qo : Ko;
                *reinterpret_cast<float2*>(
                    C + ((((size_t)b0 * NH + h_) * SEQ + s0) * HD + hd_)) = make_float2(v0, v1);
                *reinterpret_cast<float2*>(
                    C + ((((size_t)b1 * NH + h_) * SEQ + s1) * HD + hd_)) = make_float2(v2, v3);
            }
        }
    }
}

// Output projection: plain row-major out.
__global__ __launch_bounds__(256) void gemm_out(const float* __restrict__ A,
                                                const float* __restrict__ W,
                                                float* __restrict__ C)
{
    extern __shared__ float sm[];
    uint32_t smb = smem_u32(sm);
    int tid = threadIdx.x;
    int m0 = blockIdx.y * 128, n0 = blockIdx.x * 128;

    float acc[4][4][4];
#pragma unroll
    for (int i = 0; i < 4; ++i)
#pragma unroll
        for (int j = 0; j < 4; ++j)
#pragma unroll
            for (int r = 0; r < 4; ++r) acc[i][j][r] = 0.f;

    gemm_body(A, W, smb, tid, m0, n0, acc);

    int lane = tid & 31;
    int w = tid >> 5, wm = w >> 2, wn = w & 3;
    int g = lane >> 2, tg = lane & 3;
#pragma unroll
    for (int mi = 0; mi < 4; ++mi) {
#pragma unroll
        for (int nj = 0; nj < 4; ++nj) {
            int m = m0 + wm * 64 + mi * 16 + g;
            int n = n0 + wn * 32 + nj * 8 + 2 * tg;
            *reinterpret_cast<float2*>(C + (size_t)m * DMODEL + n) =
                make_float2(acc[mi][nj][0], acc[mi][nj][1]);
            *reinterpret_cast<float2*>(C + (size_t)(m + 8) * DMODEL + n) =
                make_float2(acc[mi][nj][2], acc[mi][nj][3]);
        }
    }
}

// ================= tensor-core flash attention, 2 CTAs/SM, all-ldmatrix ======
// KV tile 32. V transposed in smem: 128 d-rows x (32+4) t-cols.
#define KVT   32
#define DPADK 132
#define VTPAD 36
#define QPAD  132
#define PPAD  36
#define AT_K    0
#define AT_V    (2 * KVT * DPADK)                 // 8448
#define AT_QS   (AT_V + 2 * HD * VTPAD)           // 8448 + 9216 = 17664
#define AT_PS   (AT_QS + 64 * QPAD)               // 26112
#define AT_LROW (AT_PS + 64 * PPAD)               // 28416
#define ATTN_SMEM ((AT_LROW + 64) * 4)            // 113920 B

__device__ __forceinline__ void load_kv32(const float* __restrict__ kcb,
                                          const float* __restrict__ knb,
                                          const float* __restrict__ vtb,
                                          int t0, int st, uint32_t smb, int tid)
{
    uint32_t sk = smb + (uint32_t)((AT_K + st * KVT * DPADK) * 4);
    uint32_t sv = smb + (uint32_t)((AT_V + st * HD * VTPAD) * 4);
    // K: 32 t-rows x 128 d
#pragma unroll
    for (int i = 0; i < 4; ++i) {
        int idx = tid + 256 * i;          // 0..1023
        int row = idx >> 5;               // 0..31
        int j = idx & 31;
        int t = t0 + row;
        const float* ks = (t < CACHEDLEN) ? kcb + (size_t)t * HD
                                          : knb + (size_t)(t - CACHEDLEN) * HD;
        cp_async16(sk + (uint32_t)(row * (DPADK * 4) + j * 16), ks + j * 4);
    }
    // V^T: 128 d-rows x 32 t (unified buffer, no branch)
#pragma unroll
    for (int i = 0; i < 4; ++i) {
        int idx = tid + 256 * i;          // 0..1023
        int row = idx >> 3;               // 0..127 (d)
        int ch = idx & 7;                 // 16B chunk within 32 t
        cp_async16(sv + (uint32_t)(row * (VTPAD * 4) + ch * 16),
                   vtb + (size_t)row * TTOT + t0 + ch * 4);
    }
}

__global__ __launch_bounds__(256, 2) void attn_tc(
    const float* __restrict__ Q,
    const float* __restrict__ Kn,
    const float* __restrict__ kc,
    const float* __restrict__ vt,
    float* __restrict__ O)
{
    extern __shared__ float sm[];
    uint32_t smb = smem_u32(sm);
    float* Ps   = sm + AT_PS;
    float* lrow = sm + AT_LROW;
    uint32_t qsb = smb + AT_QS * 4;
    uint32_t psb = smb + AT_PS * 4;

    int qt = blockIdx.x, h = blockIdx.y, b = blockIdx.z;
    int tid = threadIdx.x, lane = tid & 31, w = tid >> 5;
    int wm = w >> 1, wn = w & 1;
    int g = lane >> 2, tg = lane & 3;
    int q0 = qt * 64;
    size_t bh = (size_t)b * NH + h;

    if (tid < 64) lrow[tid] = 0.f;

    // ldmatrix lane offsets
    int lr16 = lane & 15;
    int lc4  = ((lane >> 4) & 1) * 4;
    int br   = (lane & 7) + ((lane >> 4) & 1) * 8;
    int bc4  = ((lane >> 3) & 1) * 4;
    uint32_t a_off = (uint32_t)(((wm * 16 + lr16) * QPAD + lc4) * 4);
    uint32_t k_off = (uint32_t)(((wn * 16 + br) * DPADK + bc4) * 4);
    uint32_t p_off = (uint32_t)(((wm * 16 + lr16) * PPAD + lc4) * 4);
    uint32_t v_off[4];
#pragma unroll
    for (int njp = 0; njp < 4; ++njp)
        v_off[njp] = (uint32_t)(((wn * 64 + njp * 16 + br) * VTPAD + bc4) * 4);

    const float* kcb = kc + bh * CACHEDLEN * HD;
    const float* knb = Kn + bh * SEQ * HD;
    const float* vtb = vt + bh * HD * TTOT;

    // Q tile -> smem
    const float* Qg = Q + (bh * SEQ + q0) * HD;
#pragma unroll
    for (int i = 0; i < 8; ++i) {
        int idx = tid + 256 * i;
        int row = idx >> 5;
        int j = idx & 31;
        cp_async16(qsb + (uint32_t)(row * (QPAD * 4) + j * 16),
                   Qg + (size_t)row * HD + j * 4);
    }

    float oa[8][4];
#pragma unroll
    for (int j = 0; j < 8; ++j)
#pragma unroll
        for (int r = 0; r < 4; ++r) oa[j][r] = 0.f;

    int nt = (CACHEDLEN + q0 + 64) / KVT;
    load_kv32(kcb, knb, vtb, 0, 0, smb, tid);
    CP_COMMIT();

    for (int it = 0; it < nt; ++it) {
        if (it + 1 < nt)
            load_kv32(kcb, knb, vtb, (it + 1) * KVT, (it + 1) & 1, smb, tid);
        CP_COMMIT();
        CP_WAIT1();
        __syncthreads();

        uint32_t sK = smb + (uint32_t)((AT_K + (it & 1) * KVT * DPADK) * 4);
        uint32_t sV = smb + (uint32_t)((AT_V + (it & 1) * HD * VTPAD) * 4);

        // ---- S = Q K^T : warp tile 16x16 ----
        float sc[2][4];
#pragma unroll
        for (int nj = 0; nj < 2; ++nj)
#pragma unroll
            for (int r = 0; r < 4; ++r) sc[nj][r] = 0.f;

#pragma unroll
        for (int s = 0; s < 16; ++s) {
            uint32_t koff = (uint32_t)(s * 32);
            uint32_t af[4], kq[4];
            ldsm_x4(af, qsb + a_off + koff);
            ldsm_x4(kq, sK + k_off + koff);
            mma_tf32(sc[0], af, &kq[0]);
            mma_tf32(sc[1], af, &kq[2]);
        }

        // ---- exp + mask + row sums + store P (tf32-rounded) ----
        int qa0 = CACHEDLEN + q0 + wm * 16 + g;
        int tb  = it * KVT + wn * 16;
        float rs0 = 0.f, rs1 = 0.f;
#pragma unroll
        for (int nj = 0; nj < 2; ++nj) {
            int c0 = tb + nj * 8 + 2 * tg;
            float p00 = (c0     <= qa0    ) ? roundtf(__expf(sc[nj][0])) : 0.f;
            float p01 = (c0 + 1 <= qa0    ) ? roundtf(__expf(sc[nj][1])) : 0.f;
            float p10 = (c0     <= qa0 + 8) ? roundtf(__expf(sc[nj][2])) : 0.f;
            float p11 = (c0 + 1 <= qa0 + 8) ? roundtf(__expf(sc[nj][3])) : 0.f;
            rs0 += p00 + p01;
            rs1 += p10 + p11;
            int pr = wm * 16 + g;
            int pcol = wn * 16 + nj * 8 + 2 * tg;
            *reinterpret_cast<float2*>(&Ps[pr * PPAD + pcol])       = make_float2(p00, p01);
            *reinterpret_cast<float2*>(&Ps[(pr + 8) * PPAD + pcol]) = make_float2(p10, p11);
        }
        rs0 += __shfl_xor_sync(0xffffffffu, rs0, 1);
        rs0 += __shfl_xor_sync(0xffffffffu, rs0, 2);
        rs1 += __shfl_xor_sync(0xffffffffu, rs1, 1);
        rs1 += __shfl_xor_sync(0xffffffffu, rs1, 2);
        if (tg == 0) {
            atomicAdd(&lrow[wm * 16 + g], rs0);
            atomicAdd(&lrow[wm * 16 + g + 8], rs1);
        }
        __syncthreads();

        // ---- O += P V : all fragments via ldmatrix ----
#pragma unroll
        for (int s = 0; s < 4; ++s) {
            uint32_t koff = (uint32_t)(s * 32);
            uint32_t pq[4];
            ldsm_x4(pq, psb + p_off + koff);
            uint32_t vq[4][4];
#pragma unroll
            for (int njp = 0; njp < 4; ++njp)
                ldsm_x4(vq[njp], sV + v_off[njp] + koff);
#pragma unroll
            for (int nj = 0; nj < 8; ++nj)
                mma_tf32(oa[nj], pq, &vq[nj >> 1][(nj & 1) * 2]);
        }
        __syncthreads();
    }

    float inv0 = 1.f / lrow[wm * 16 + g];
    float inv1 = 1.f / lrow[wm * 16 + g + 8];
    int row0 = q0 + wm * 16 + g;
#pragma unroll
    for (int nj = 0; nj < 8; ++nj) {
        int d = wn * 64 + nj * 8 + 2 * tg;
        float* dst0 = O + ((size_t)b * SEQ + row0) * DMODEL + h * HD + d;
        float* dst1 = O + ((size_t)b * SEQ + row0 + 8) * DMODEL + h * HD + d;
        *reinterpret_cast<float2*>(dst0) =
            make_float2(roundtf(oa[nj][0] * inv0), roundtf(oa[nj][1] * inv0));
        *reinterpret_cast<float2*>(dst1) =
            make_float2(roundtf(oa[nj][2] * inv1), roundtf(oa[nj][3] * inv1));
    }
}

// ---------------- launch ----------------
extern "C" void kernel_launch(void* const* d_in, const int* in_sizes, int n_in,
                              void* d_out, int out_size)
{
    const float* X  = (const float*)d_in[0];
    const float* Wq = (const float*)d_in[1];
    const float* Wk = (const float*)d_in[2];
    const float* Wv = (const float*)d_in[3];
    const float* Wo = (const float*)d_in[4];
    const float* kc = (const float*)d_in[5];
    const float* vc = (const float*)d_in[6];

    float *Qp, *Kp, *Vtp, *Ap, *Xp, *Wp, *Kcp;
    cudaGetSymbolAddress((void**)&Qp,  g_Q);
    cudaGetSymbolAddress((void**)&Kp,  g_Kn);
    cudaGetSymbolAddress((void**)&Vtp, g_Vt);
    cudaGetSymbolAddress((void**)&Ap,  g_At);
    cudaGetSymbolAddress((void**)&Xp,  g_X);
    cudaGetSymbolAddress((void**)&Wp,  g_Wr);
    cudaGetSymbolAddress((void**)&Kcp, g_Kc);

    cudaFuncSetAttribute(gemm_qkv, cudaFuncAttributeMaxDynamicSharedMemorySize, GEMM_SMEM);
    cudaFuncSetAttribute(gemm_out, cudaFuncAttributeMaxDynamicSharedMemorySize, GEMM_SMEM);
    cudaFuncSetAttribute(attn_tc,  cudaFuncAttributeMaxDynamicSharedMemorySize, ATTN_SMEM);

    const int NX = BATCH * SEQ * DMODEL / 4;
    const int NW = DMODEL * DMODEL / 4;
    const int NC = BATCH * NH * CACHEDLEN * HD / 4;

    round_tf32_k<<<NX / 1024, 256>>>((const float4*)X,  (float4*)Xp,  NX);
    round_tf32_k<<<NW / 1024, 256>>>((const float4*)Wq, (float4*)(Wp + 0L * DMODEL * DMODEL), NW);
    round_tf32_k<<<NW / 1024, 256>>>((const float4*)Wk, (float4*)(Wp + 1L * DMODEL * DMODEL), NW);
    round_tf32_k<<<NW / 1024, 256>>>((const float4*)Wv, (float4*)(Wp + 2L * DMODEL * DMODEL), NW);
    round_tf32_k<<<NW / 1024, 256>>>((const float4*)Wo, (float4*)(Wp + 3L * DMODEL * DMODEL), NW);
    round_tf32_k<<<NC / 1024, 256>>>((const float4*)kc, (float4*)Kcp, NC);
    vtrans_round_k<<<dim3(CACHEDLEN / 32, HD / 32, BATCH * NH), 256>>>(vc, Vtp);

    dim3 gq(DMODEL / 128, (BATCH * SEQ) / 128, 3);   // fused QKV
    gemm_qkv<<<gq, 256, GEMM_SMEM>>>(Xp, Wp, Qp, Kp, Vtp);

    attn_tc<<<dim3(SEQ / 64, NH, BATCH), 256, ATTN_SMEM>>>(Qp, Kp, Kcp, Vtp, Ap);

    dim3 gg(DMODEL / 128, (BATCH * SEQ) / 128);
    gemm_out<<<gg, 256, GEMM_SMEM>>>(Ap, Wp + 3L * DMODEL * DMODEL, (float*)d_out);
}